// round 4
// baseline (speedup 1.0000x reference)
#include <cuda_runtime.h>
#include <math.h>

#define NROWS 16384
#define DIN   64
#define HDIM  256
#define LOUT  64
#define NEXP  256
#define TM    64
#define MAXT  (NROWS / TM + NEXP)   // 512 upper bound on tiles

// ---- scratch (no allocations allowed) ----
__device__ int g_cnt[NEXP];
__device__ int g_off[NEXP];
__device__ int g_cur[NEXP];
__device__ int g_sorted[NROWS];
__device__ int g_te[MAXT];
__device__ int g_tr0[MAXT];
__device__ int g_trn[MAXT];

// ---------------- sort/plan kernels ----------------
__global__ void k_prep() { g_cnt[threadIdx.x] = 0; }

__global__ void k_hist(const int* __restrict__ ind) {
    int n = blockIdx.x * blockDim.x + threadIdx.x;
    atomicAdd(&g_cnt[ind[n]], 1);
}

__global__ void k_plan() {
    __shared__ int sc[NEXP];
    int t = threadIdx.x;
    int c = g_cnt[t];
    sc[t] = c; __syncthreads();
    for (int s = 1; s < NEXP; s <<= 1) {
        int v = (t >= s) ? sc[t - s] : 0;
        __syncthreads();
        sc[t] += v;
        __syncthreads();
    }
    int off = sc[t] - c;
    g_off[t] = off;
    g_cur[t] = off;
    int nt = (c + TM - 1) / TM;
    __syncthreads();
    sc[t] = nt; __syncthreads();
    for (int s = 1; s < NEXP; s <<= 1) {
        int v = (t >= s) ? sc[t - s] : 0;
        __syncthreads();
        sc[t] += v;
        __syncthreads();
    }
    int tb = sc[t] - nt;
    for (int i = t; i < MAXT; i += NEXP) g_trn[i] = 0;
    __syncthreads();
    for (int j = 0; j < nt; j++) {
        g_te[tb + j]  = t;
        g_tr0[tb + j] = off + j * TM;
        g_trn[tb + j] = min(TM, c - j * TM);
    }
}

__global__ void k_scatter(const int* __restrict__ ind) {
    int n = blockIdx.x * blockDim.x + threadIdx.x;
    int e = ind[n];
    int p = atomicAdd(&g_cur[e], 1);
    g_sorted[p] = n;
}

// ---------------- f32x2 + cp.async helpers ----------------
__device__ __forceinline__ unsigned long long bcast2(float v) {
    unsigned long long r;
    asm("mov.b64 %0, {%1, %1};" : "=l"(r) : "f"(v));
    return r;
}
__device__ __forceinline__ void fma2(unsigned long long& a,
                                     unsigned long long b, unsigned long long c) {
    asm("fma.rn.f32x2 %0, %1, %2, %0;" : "+l"(a) : "l"(b), "l"(c));
}
__device__ __forceinline__ float2 unpack2(unsigned long long a) {
    float2 f;
    asm("mov.b64 {%0, %1}, %2;" : "=f"(f.x), "=f"(f.y) : "l"(a));
    return f;
}
__device__ __forceinline__ void cpa4(unsigned int dst, const float* src) {
    asm volatile("cp.async.ca.shared.global [%0], [%1], 4;" :: "r"(dst), "l"(src));
}
#define CP_COMMIT() asm volatile("cp.async.commit_group;")
#define CP_WAIT(n)  asm volatile("cp.async.wait_group %0;" :: "n"(n))

// ---------------- main MLP kernel ----------------
// smem (floats): WsA[16384] | WsB[16384] | H[16384] | Xs[4096] | rows[64 ints]
// = 208.25 KB. H holds H1 during stage 2, is overwritten with H2 after (post-sync).
#define OFF_WSA 0
#define OFF_WSB 16384
#define OFF_H   32768
#define OFF_XS  49152
#define OFF_ROWS 53248
#define SMEM_BYTES (53248 * 4 + TM * 4)

// Prefetch a transposed 64-k slab of W2 ([k<64][o<256]) into smem buffer at byte-addr sbuf.
__device__ __forceinline__ void prefetch_w2(const float* __restrict__ W2, int e, int kt,
                                            unsigned int sbuf, int tid) {
    const float* src = W2 + (size_t)e * HDIM * HDIM + (size_t)tid * HDIM + kt * 64;
    unsigned int dst = sbuf + tid * 4;
    #pragma unroll
    for (int c = 0; c < 64; c++) cpa4(dst + c * (HDIM * 4), src + c);
}
// Prefetch transposed Wl ([k<256][o<64]) into buffer at byte-addr sbuf.
__device__ __forceinline__ void prefetch_wl(const float* __restrict__ Wl, int e,
                                            unsigned int sbuf, int tid) {
    int o = tid & 63, q = tid >> 6;
    const float* src = Wl + (size_t)e * LOUT * HDIM + (size_t)o * HDIM + q * 64;
    unsigned int dst = sbuf + ((q * 64) * 64 + o) * 4;
    #pragma unroll
    for (int c = 0; c < 64; c++) cpa4(dst + c * (64 * 4), src + c);
}

__global__ __launch_bounds__(256, 1)
void k_mlp(const float* __restrict__ x,
           const float* __restrict__ W1, const float* __restrict__ b1,
           const float* __restrict__ W2, const float* __restrict__ b2,
           const float* __restrict__ Wl, const float* __restrict__ bl,
           float* __restrict__ out)
{
    int bid = blockIdx.x;
    int M = g_trn[bid];
    if (M == 0) return;
    int e  = g_te[bid];
    int r0 = g_tr0[bid];

    extern __shared__ float sm[];
    float* WsA = sm + OFF_WSA;
    float* WsB = sm + OFF_WSB;
    float* H   = sm + OFF_H;
    float* Xs  = sm + OFF_XS;
    int*  rows = (int*)(sm + OFF_ROWS);
    unsigned int sb = (unsigned int)__cvta_generic_to_shared(sm);
    unsigned int sbA = sb + OFF_WSA * 4, sbB = sb + OFF_WSB * 4;

    int tid = threadIdx.x;

    if (tid < TM)
        rows[tid] = g_sorted[r0 + ((tid < M) ? tid : 0)];

    // ---- async W1 slab -> WsA (transposed [k<64][o<256]) ----
    {
        const float* src = W1 + (size_t)e * HDIM * DIN + (size_t)tid * DIN;
        unsigned int dst = sbA + tid * 4;
        #pragma unroll
        for (int c = 0; c < DIN; c++) cpa4(dst + c * (HDIM * 4), src + c);
    }
    CP_COMMIT();
    // ---- async W2 kt=0 slab -> WsB ----
    prefetch_w2(W2, e, 0, sbB, tid);
    CP_COMMIT();

    // ---- X tile: Xs[m][k], direct loads ----
    #pragma unroll
    for (int it = 0; it < 4; it++) {
        int idx = tid + it * 256;
        int m = idx >> 4, ch = idx & 15;
        int row = g_sorted[r0 + ((m < M) ? m : 0)];
        float4 v = ((const float4*)(x + (size_t)row * DIN))[ch];
        ((float4*)(Xs + m * DIN))[ch] = v;
    }

    CP_WAIT(1);           // W1 arrived (W2 kt0 may still be in flight)
    __syncthreads();

    int og = tid & 63, mg = tid >> 6;
    int o0 = og * 4, m0 = mg * 16;

    // ================= stage 1: h1 = tanh(W1 @ x + b1) =================
    unsigned long long accA[16], accB[16];   // accA: (o0,o0+1), accB: (o0+2,o0+3)
    #pragma unroll
    for (int j = 0; j < 16; j++) { accA[j] = 0ull; accB[j] = 0ull; }

    #pragma unroll 1
    for (int kk = 0; kk < 16; kk++) {
        ulonglong2 wp[4];
        #pragma unroll
        for (int dk = 0; dk < 4; dk++)
            wp[dk] = *reinterpret_cast<const ulonglong2*>(&WsA[(kk * 4 + dk) * HDIM + o0]);
        #pragma unroll
        for (int j = 0; j < 16; j++) {
            float4 h4 = *reinterpret_cast<const float4*>(&Xs[(m0 + j) * DIN + kk * 4]);
            unsigned long long h;
            h = bcast2(h4.x); fma2(accA[j], wp[0].x, h); fma2(accB[j], wp[0].y, h);
            h = bcast2(h4.y); fma2(accA[j], wp[1].x, h); fma2(accB[j], wp[1].y, h);
            h = bcast2(h4.z); fma2(accA[j], wp[2].x, h); fma2(accB[j], wp[2].y, h);
            h = bcast2(h4.w); fma2(accA[j], wp[3].x, h); fma2(accB[j], wp[3].y, h);
        }
    }
    __syncthreads();                 // all warps done reading WsA -> free for kt=1

    prefetch_w2(W2, e, 1, sbA, tid); // overlap with epilogue + kt0 compute
    CP_COMMIT();

    {   // epilogue: bias + tanh -> H (H1)
        float bb0 = b1[e * HDIM + o0 + 0], bb1 = b1[e * HDIM + o0 + 1];
        float bb2 = b1[e * HDIM + o0 + 2], bb3 = b1[e * HDIM + o0 + 3];
        #pragma unroll
        for (int j = 0; j < 16; j++) {
            float2 p = unpack2(accA[j]), q = unpack2(accB[j]);
            float4 v;
            v.x = tanhf(p.x + bb0); v.y = tanhf(p.y + bb1);
            v.z = tanhf(q.x + bb2); v.w = tanhf(q.y + bb3);
            *(float4*)&H[(m0 + j) * HDIM + o0] = v;
        }
    }
    CP_WAIT(1);           // W2 kt0 arrived
    __syncthreads();      // H1 visible, WsB ready

    // ================= stage 2: h2 = tanh(W2 @ h1 + b2) =================
    #pragma unroll
    for (int j = 0; j < 16; j++) { accA[j] = 0ull; accB[j] = 0ull; }

    int cur = 1;          // kt0 lives in WsB
    #pragma unroll 1
    for (int kt = 0; kt < 4; kt++) {
        const float* Wc = cur ? WsB : WsA;
        #pragma unroll 1
        for (int kk = 0; kk < 16; kk++) {
            ulonglong2 wp[4];
            #pragma unroll
            for (int dk = 0; dk < 4; dk++)
                wp[dk] = *reinterpret_cast<const ulonglong2*>(&Wc[(kk * 4 + dk) * HDIM + o0]);
            #pragma unroll
            for (int j = 0; j < 16; j++) {
                float4 h4 = *reinterpret_cast<const float4*>(&H[(m0 + j) * HDIM + kt * 64 + kk * 4]);
                unsigned long long h;
                h = bcast2(h4.x); fma2(accA[j], wp[0].x, h); fma2(accB[j], wp[0].y, h);
                h = bcast2(h4.y); fma2(accA[j], wp[1].x, h); fma2(accB[j], wp[1].y, h);
                h = bcast2(h4.z); fma2(accA[j], wp[2].x, h); fma2(accB[j], wp[2].y, h);
                h = bcast2(h4.w); fma2(accA[j], wp[3].x, h); fma2(accB[j], wp[3].y, h);
            }
        }
        __syncthreads();  // current buffer free
        if (kt < 2) {
            prefetch_w2(W2, e, kt + 2, cur ? sbB : sbA, tid);
            CP_COMMIT(); CP_WAIT(1); __syncthreads();
        } else if (kt == 2) {
            prefetch_wl(Wl, e, cur ? sbB : sbA, tid);
            CP_COMMIT(); CP_WAIT(1); __syncthreads();
        }
        cur ^= 1;
    }
    // after loop: cur==1 -> WsB holds Wl (still possibly in flight)

    {   // epilogue: bias + tanh -> H (H2 overwrites H1; all reads done, synced)
        float bb0 = b2[e * HDIM + o0 + 0], bb1 = b2[e * HDIM + o0 + 1];
        float bb2 = b2[e * HDIM + o0 + 2], bb3 = b2[e * HDIM + o0 + 3];
        #pragma unroll
        for (int j = 0; j < 16; j++) {
            float2 p = unpack2(accA[j]), q = unpack2(accB[j]);
            float4 v;
            v.x = tanhf(p.x + bb0); v.y = tanhf(p.y + bb1);
            v.z = tanhf(q.x + bb2); v.w = tanhf(q.y + bb3);
            *(float4*)&H[(m0 + j) * HDIM + o0] = v;
        }
    }
    CP_WAIT(0);           // Wl slab arrived
    __syncthreads();      // H2 + Wl visible

    // ================= stage 3: out = Wl @ h2 + bl =================
    {
        int og3 = tid & 15, mg3 = tid >> 4;
        int p0 = og3 * 4, n0 = mg3 * 4;
        unsigned long long cA[4], cB[4];
        #pragma unroll
        for (int j = 0; j < 4; j++) { cA[j] = 0ull; cB[j] = 0ull; }

        #pragma unroll 1
        for (int kk = 0; kk < 64; kk++) {
            ulonglong2 wp[4];
            #pragma unroll
            for (int dk = 0; dk < 4; dk++)
                wp[dk] = *reinterpret_cast<const ulonglong2*>(&WsB[(kk * 4 + dk) * LOUT + p0]);
            #pragma unroll
            for (int j = 0; j < 4; j++) {
                float4 h4 = *reinterpret_cast<const float4*>(&H[(n0 + j) * HDIM + kk * 4]);
                unsigned long long h;
                h = bcast2(h4.x); fma2(cA[j], wp[0].x, h); fma2(cB[j], wp[0].y, h);
                h = bcast2(h4.y); fma2(cA[j], wp[1].x, h); fma2(cB[j], wp[1].y, h);
                h = bcast2(h4.z); fma2(cA[j], wp[2].x, h); fma2(cB[j], wp[2].y, h);
                h = bcast2(h4.w); fma2(cA[j], wp[3].x, h); fma2(cB[j], wp[3].y, h);
            }
        }

        float bb0 = bl[e * LOUT + p0 + 0], bb1 = bl[e * LOUT + p0 + 1];
        float bb2 = bl[e * LOUT + p0 + 2], bb3 = bl[e * LOUT + p0 + 3];
        #pragma unroll
        for (int j = 0; j < 4; j++) {
            int m = n0 + j;
            if (m < M) {
                float2 p = unpack2(cA[j]), q = unpack2(cB[j]);
                float4 v;
                v.x = p.x + bb0; v.y = p.y + bb1;
                v.z = q.x + bb2; v.w = q.y + bb3;
                *(float4*)&out[(size_t)rows[m] * LOUT + p0] = v;
            }
        }
    }
}

// ---------------- launch ----------------
extern "C" void kernel_launch(void* const* d_in, const int* in_sizes, int n_in,
                              void* d_out, int out_size) {
    (void)in_sizes; (void)n_in; (void)out_size;
    const float* x  = (const float*)d_in[0];
    const int*   nd = (const int*)  d_in[1];
    const float* W1 = (const float*)d_in[2];
    const float* b1 = (const float*)d_in[3];
    const float* W2 = (const float*)d_in[4];
    const float* b2 = (const float*)d_in[5];
    const float* Wl = (const float*)d_in[6];
    const float* bl = (const float*)d_in[7];
    float* out = (float*)d_out;

    cudaFuncSetAttribute(k_mlp, cudaFuncAttributeMaxDynamicSharedMemorySize, SMEM_BYTES);

    k_prep<<<1, NEXP>>>();
    k_hist<<<NROWS / 256, 256>>>(nd);
    k_plan<<<1, NEXP>>>();
    k_scatter<<<NROWS / 256, 256>>>(nd);
    k_mlp<<<MAXT, 256, SMEM_BYTES>>>(x, W1, b1, W2, b2, Wl, bl, out);
}

// round 9
// speedup vs baseline: 4.5978x; 4.5978x over previous
#include <cuda_runtime.h>
#include <cstdint>
#include <math.h>

#define NROWS 16384
#define DIN   64
#define HDIM  256
#define LOUT  64
#define NEXP  256
#define TM    64
#define MAXT  (NROWS / TM + NEXP)

#define SX  68    // Xs row stride (floats)
#define SW  68    // W slab row stride
#define SH  260   // H row stride
#define SWL 260   // Wl row stride

// ---- scratch ----
__device__ int g_cnt[NEXP];
__device__ int g_cur[NEXP];
__device__ int g_sorted[NROWS];
__device__ int g_te[MAXT];
__device__ int g_tr0[MAXT];
__device__ int g_trn[MAXT];

// ---------------- sort/plan ----------------
__global__ void k_hist(const int* __restrict__ ind) {
    int n = blockIdx.x * blockDim.x + threadIdx.x;
    atomicAdd(&g_cnt[ind[n]], 1);
}

__global__ void k_plan() {
    __shared__ int sc[NEXP];
    int t = threadIdx.x;
    int c = g_cnt[t];
    g_cnt[t] = 0;                       // re-zero for next graph replay
    sc[t] = c; __syncthreads();
    for (int s = 1; s < NEXP; s <<= 1) {
        int v = (t >= s) ? sc[t - s] : 0;
        __syncthreads(); sc[t] += v; __syncthreads();
    }
    int off = sc[t] - c;
    g_cur[t] = off;
    int nt = (c + TM - 1) / TM;
    __syncthreads();
    sc[t] = nt; __syncthreads();
    for (int s = 1; s < NEXP; s <<= 1) {
        int v = (t >= s) ? sc[t - s] : 0;
        __syncthreads(); sc[t] += v; __syncthreads();
    }
    int tb = sc[t] - nt;
    for (int i = t; i < MAXT; i += NEXP) g_trn[i] = 0;
    __syncthreads();
    for (int j = 0; j < nt; j++) {
        g_te[tb + j]  = t;
        g_tr0[tb + j] = off + j * TM;
        g_trn[tb + j] = min(TM, c - j * TM);
    }
}

__global__ void k_scatter(const int* __restrict__ ind) {
    int n = blockIdx.x * blockDim.x + threadIdx.x;
    int e = ind[n];
    int p = atomicAdd(&g_cur[e], 1);
    g_sorted[p] = n;
}

// ---------------- helpers (all sm_80-baseline PTX) ----------------
static __device__ __forceinline__ uint32_t f2tf(float f) {
    uint32_t r; asm("cvt.rna.tf32.f32 %0, %1;" : "=r"(r) : "f"(f)); return r;
}
static __device__ __forceinline__ void mma8(float* c, const uint32_t* a, const uint32_t* b) {
    asm("mma.sync.aligned.m16n8k8.row.col.f32.tf32.tf32.f32 "
        "{%0,%1,%2,%3}, {%4,%5,%6,%7}, {%8,%9}, {%0,%1,%2,%3};"
        : "+f"(c[0]), "+f"(c[1]), "+f"(c[2]), "+f"(c[3])
        : "r"(a[0]), "r"(a[1]), "r"(a[2]), "r"(a[3]), "r"(b[0]), "r"(b[1]));
}
static __device__ __forceinline__ void cp16(uint32_t dst, const float* src) {
    asm volatile("cp.async.cg.shared.global [%0], [%1], 16;" :: "r"(dst), "l"(src));
}
#define CP_COMMIT() asm volatile("cp.async.commit_group;")
#define CP_WAIT0()  asm volatile("cp.async.wait_group 0;")
#define CP_WAIT1()  asm volatile("cp.async.wait_group 1;")

static __device__ __forceinline__ float mytanh(float x) {
    float xc = fminf(fmaxf(x, -15.f), 15.f);
    float e = __expf(2.f * xc);
    return __fdividef(e - 1.f, e + 1.f);
}

// One 64-k block of a [64m x (o: w*32..w*32+32)] GEMM chunk.
template<int SA, int SB_>
static __device__ __forceinline__ void mm64(const float* __restrict__ A,
                                            const float* __restrict__ B,
                                            int g, int t, int w,
                                            float acc[4][4][4]) {
    #pragma unroll
    for (int kk = 0; kk < 8; kk++) {
        int k0 = kk * 8;
        uint32_t a[4][4];
        #pragma unroll
        for (int mt = 0; mt < 4; mt++) {
            const float* p = A + (mt * 16 + g) * SA + k0 + t;
            a[mt][0] = f2tf(p[0]);          a[mt][1] = f2tf(p[8 * SA]);
            a[mt][2] = f2tf(p[4]);          a[mt][3] = f2tf(p[8 * SA + 4]);
        }
        uint32_t b[4][2];
        #pragma unroll
        for (int ot = 0; ot < 4; ot++) {
            const float* p = B + (w * 32 + ot * 8 + g) * SB_ + k0 + t;
            b[ot][0] = f2tf(p[0]);          b[ot][1] = f2tf(p[4]);
        }
        #pragma unroll
        for (int mt = 0; mt < 4; mt++)
            #pragma unroll
            for (int ot = 0; ot < 4; ot++)
                mma8(acc[mt][ot], a[mt], b[ot]);
    }
}

// ---------------- SMEM map (floats) ----------------
#define OXS   0                     // 64 x 68      = 4352
#define OH    4352                  // 64 x 260     = 16640  (H1, then H2)
#define OWA   20992                 // 256 x 68     = 17408
#define OWB   38400                 // 256 x 68     = 17408
#define OROWS 55808                 // 64 ints
#define SMEM_FLOATS 55872
#define SMEM_BYTES  (SMEM_FLOATS * 4)

static __device__ __forceinline__ void cp_w2slab(const float* __restrict__ W2e, int kt,
                                                 uint32_t ubuf, int tid) {
    #pragma unroll
    for (int i = 0; i < 16; i++) {
        int c = tid + i * 256; int r = c >> 4, kc = (c & 15) << 2;
        cp16(ubuf + (r * SW + kc) * 4, W2e + r * HDIM + kt * 64 + kc);
    }
}

// ---------------- main kernel ----------------
__global__ __launch_bounds__(256, 1)
void k_mlp(const float* __restrict__ x,
           const float* __restrict__ W1, const float* __restrict__ b1,
           const float* __restrict__ W2, const float* __restrict__ b2,
           const float* __restrict__ Wl, const float* __restrict__ bl,
           float* __restrict__ out)
{
    int bid = blockIdx.x;
    int M = g_trn[bid];
    if (M == 0) return;
    int e  = g_te[bid];
    int r0 = g_tr0[bid];

    extern __shared__ float sm[];
    float* Xs = sm + OXS;
    float* H  = sm + OH;
    float* WA = sm + OWA;
    float* WB = sm + OWB;
    int* rows = (int*)(sm + OROWS);
    uint32_t sb = (uint32_t)__cvta_generic_to_shared(sm);
    uint32_t uXS = sb + OXS * 4, uWA = sb + OWA * 4, uWB = sb + OWB * 4;

    int tid = threadIdx.x;
    int w = tid >> 5, lane = tid & 31, g = lane >> 2, t = lane & 3;

    const float* W1e = W1 + (size_t)e * HDIM * DIN;
    const float* W2e = W2 + (size_t)e * HDIM * HDIM;
    const float* Wle = Wl + (size_t)e * LOUT * HDIM;

    // ---- P0: X + W1 (group), W2 slab0 (group) ----
    #pragma unroll
    for (int i = 0; i < 4; i++) {
        int c = tid + i * 256;
        int m = c >> 4, kc = (c & 15) << 2;
        int row = g_sorted[r0 + ((m < M) ? m : (M - 1))];
        cp16(uXS + (m * SX + kc) * 4, x + (size_t)row * DIN + kc);
    }
    #pragma unroll
    for (int i = 0; i < 16; i++) {
        int c = tid + i * 256; int r = c >> 4, kc = (c & 15) << 2;
        cp16(uWA + (r * SW + kc) * 4, W1e + r * DIN + kc);
    }
    CP_COMMIT();
    cp_w2slab(W2e, 0, uWB, tid);
    CP_COMMIT();

    if (tid < TM) rows[tid] = g_sorted[r0 + ((tid < M) ? tid : (M - 1))];

    float acc[4][4][4];
    #pragma unroll
    for (int mt = 0; mt < 4; mt++)
        #pragma unroll
        for (int ot = 0; ot < 4; ot++)
            #pragma unroll
            for (int i = 0; i < 4; i++) acc[mt][ot][i] = 0.f;

    CP_WAIT0();
    __syncthreads();

    // ================= stage 1: H1 = tanh(X @ W1^T + b1) =================
    mm64<SX, SW>(Xs, WA, g, t, w, acc);
    __syncthreads();                 // WA free

    cp_w2slab(W2e, 1, uWA, tid);     // slab1 -> WA, overlaps epilogue + kt0
    CP_COMMIT();

    {   // epilogue 1
        #pragma unroll
        for (int ot = 0; ot < 4; ot++) {
            int col = w * 32 + ot * 8 + 2 * t;
            float2 bb = *(const float2*)(b1 + e * HDIM + col);
            #pragma unroll
            for (int mt = 0; mt < 4; mt++) {
                float2 v0, v1;
                v0.x = mytanh(acc[mt][ot][0] + bb.x);
                v0.y = mytanh(acc[mt][ot][1] + bb.y);
                v1.x = mytanh(acc[mt][ot][2] + bb.x);
                v1.y = mytanh(acc[mt][ot][3] + bb.y);
                *(float2*)&H[(mt * 16 + g) * SH + col]     = v0;
                *(float2*)&H[(mt * 16 + g + 8) * SH + col] = v1;
                acc[mt][ot][0] = 0.f; acc[mt][ot][1] = 0.f;
                acc[mt][ot][2] = 0.f; acc[mt][ot][3] = 0.f;
            }
        }
    }
    __syncthreads();                 // H1 visible; WB(slab0) arrived in P0 wait

    // ================= stage 2: H2 = tanh(H1 @ W2^T + b2) =================
    #pragma unroll 1
    for (int kt = 0; kt < 4; kt++) {
        const float* Wc = (kt & 1) ? WA : WB;
        uint32_t uWc = (kt & 1) ? uWA : uWB;
        mm64<SH, SW>(H + kt * 64, Wc, g, t, w, acc);
        __syncthreads();             // this buffer free
        if (kt < 2) {
            cp_w2slab(W2e, kt + 2, uWc, tid);
            CP_COMMIT(); CP_WAIT1(); __syncthreads();
        } else if (kt == 2) {
            #pragma unroll            // Wl -> WB (64 x 256, stride SWL)
            for (int i = 0; i < 16; i++) {
                int c = tid + i * 256; int r = c >> 6, kc = (c & 63) << 2;
                cp16(uWB + (r * SWL + kc) * 4, Wle + r * HDIM + kc);
            }
            CP_COMMIT(); CP_WAIT1(); __syncthreads();
        }
    }

    {   // epilogue 2: H2 overwrites H1 (all reads done; synced after kt3)
        #pragma unroll
        for (int ot = 0; ot < 4; ot++) {
            int col = w * 32 + ot * 8 + 2 * t;
            float2 bb = *(const float2*)(b2 + e * HDIM + col);
            #pragma unroll
            for (int mt = 0; mt < 4; mt++) {
                float2 v0, v1;
                v0.x = mytanh(acc[mt][ot][0] + bb.x);
                v0.y = mytanh(acc[mt][ot][1] + bb.y);
                v1.x = mytanh(acc[mt][ot][2] + bb.x);
                v1.y = mytanh(acc[mt][ot][3] + bb.y);
                *(float2*)&H[(mt * 16 + g) * SH + col]     = v0;
                *(float2*)&H[(mt * 16 + g + 8) * SH + col] = v1;
            }
        }
    }
    CP_WAIT0();                      // Wl arrived
    __syncthreads();                 // H2 + Wl visible

    // ================= stage 3: out = H2 @ Wl^T + bl =================
    {
        float a3[4][4];
        #pragma unroll
        for (int mt = 0; mt < 4; mt++)
            #pragma unroll
            for (int i = 0; i < 4; i++) a3[mt][i] = 0.f;

        #pragma unroll
        for (int kk = 0; kk < 32; kk++) {
            int k0 = kk * 8;
            uint32_t a[4][4];
            #pragma unroll
            for (int mt = 0; mt < 4; mt++) {
                const float* p = H + (mt * 16 + g) * SH + k0 + t;
                a[mt][0] = f2tf(p[0]);      a[mt][1] = f2tf(p[8 * SH]);
                a[mt][2] = f2tf(p[4]);      a[mt][3] = f2tf(p[8 * SH + 4]);
            }
            uint32_t b[2];
            {
                const float* p = WB + (w * 8 + g) * SWL + k0 + t;
                b[0] = f2tf(p[0]);          b[1] = f2tf(p[4]);
            }
            #pragma unroll
            for (int mt = 0; mt < 4; mt++)
                mma8(a3[mt], a[mt], b);
        }

        int col = w * 8 + 2 * t;
        float2 bb = *(const float2*)(bl + e * LOUT + col);
        #pragma unroll
        for (int mt = 0; mt < 4; mt++) {
            int m0g = mt * 16 + g;
            if (m0g < M) {
                float2 v; v.x = a3[mt][0] + bb.x; v.y = a3[mt][1] + bb.y;
                *(float2*)&out[(size_t)rows[m0g] * LOUT + col] = v;
            }
            if (m0g + 8 < M) {
                float2 v; v.x = a3[mt][2] + bb.x; v.y = a3[mt][3] + bb.y;
                *(float2*)&out[(size_t)rows[m0g + 8] * LOUT + col] = v;
            }
        }
    }
}

// ---------------- launch ----------------
extern "C" void kernel_launch(void* const* d_in, const int* in_sizes, int n_in,
                              void* d_out, int out_size) {
    (void)in_sizes; (void)n_in; (void)out_size;
    const float* x  = (const float*)d_in[0];
    const int*   nd = (const int*)  d_in[1];
    const float* W1 = (const float*)d_in[2];
    const float* b1 = (const float*)d_in[3];
    const float* W2 = (const float*)d_in[4];
    const float* b2 = (const float*)d_in[5];
    const float* Wl = (const float*)d_in[6];
    const float* bl = (const float*)d_in[7];
    float* out = (float*)d_out;

    cudaFuncSetAttribute(k_mlp, cudaFuncAttributeMaxDynamicSharedMemorySize, SMEM_BYTES);

    k_hist<<<NROWS / 256, 256>>>(nd);
    k_plan<<<1, NEXP>>>();
    k_scatter<<<NROWS / 256, 256>>>(nd);
    k_mlp<<<MAXT, 256, SMEM_BYTES>>>(x, W1, b1, W2, b2, Wl, bl, out);
}